// round 3
// baseline (speedup 1.0000x reference)
#include <cuda_runtime.h>
#include <cstdint>

#define B_   4
#define T_   2048
#define D_   512
#define H_   8
#define DK_  64
#define BT_  (B_ * T_)
#define DFF_ 2048

// ---------------- scratch (static device globals; no allocations) ----------
__device__ float g_h [BT_ * D_];
__device__ float g_q [BT_ * D_];   // [B,T,H,DK] flattened = [BT, 512]
__device__ float g_k [BT_ * D_];
__device__ float g_v [BT_ * D_];
__device__ float g_o [BT_ * D_];   // attention output, concat-head layout
__device__ float g_x1[BT_ * D_];
__device__ float g_h2[BT_ * D_];
__device__ float g_ff[BT_ * DFF_];

// ---------------- LayerNorm: one block per row of 512 ----------------------
__global__ __launch_bounds__(128) void ln_kernel(
    const float* __restrict__ x, const float* __restrict__ g,
    const float* __restrict__ b, float* __restrict__ out)
{
    const int row = blockIdx.x;
    const int tid = threadIdx.x;                 // 128 threads * float4 = 512
    float4 v = ((const float4*)(x + (size_t)row * D_))[tid];
    float s  = v.x + v.y + v.z + v.w;
    float ss = v.x * v.x + v.y * v.y + v.z * v.z + v.w * v.w;
    #pragma unroll
    for (int o = 16; o > 0; o >>= 1) {
        s  += __shfl_xor_sync(0xffffffffu, s,  o);
        ss += __shfl_xor_sync(0xffffffffu, ss, o);
    }
    __shared__ float sh_s[4], sh_ss[4];
    if ((tid & 31) == 0) { sh_s[tid >> 5] = s; sh_ss[tid >> 5] = ss; }
    __syncthreads();
    const float tot  = sh_s[0] + sh_s[1] + sh_s[2] + sh_s[3];
    const float tots = sh_ss[0] + sh_ss[1] + sh_ss[2] + sh_ss[3];
    const float mu   = tot  * (1.0f / D_);
    const float var  = tots * (1.0f / D_) - mu * mu;
    const float rstd = rsqrtf(var + 1e-5f);
    float4 gv = ((const float4*)g)[tid];
    float4 bv = ((const float4*)b)[tid];
    float4 r;
    r.x = (v.x - mu) * rstd * gv.x + bv.x;
    r.y = (v.y - mu) * rstd * gv.y + bv.y;
    r.z = (v.z - mu) * rstd * gv.z + bv.z;
    r.w = (v.w - mu) * rstd * gv.w + bv.w;
    ((float4*)(out + (size_t)row * D_))[tid] = r;
}

// ---------------- generic SGEMM 128x128 tile, 8x8 micro-tile ----------------
// C[row, col] = sum_k A[row, k] * B(k, col) (+bias[col]) (+res[row,col]) (relu)
// Weight addressing: addr(k, col) = Bw + (col>>6)*cstride + k*ldb + (col&63)
//   row-major [K,N]      : cstride = 64,     ldb = N
//   head-stacked [H,D,DK]: cstride = D*DK,   ldb = DK
__global__ __launch_bounds__(256) void gemm_kernel(
    const float* __restrict__ A, int lda,
    const float* __restrict__ Bw, int cstride, int ldb,
    const float* __restrict__ bias,
    const float* __restrict__ res,
    float* __restrict__ C, int ldc,
    int K, int relu)
{
    __shared__ __align__(16) float As[16][132];   // transposed: As[k][m]
    __shared__ __align__(16) float Bs[16][132];   // Bs[k][n]

    const int tid  = threadIdx.x;
    const int tx   = tid & 15;
    const int ty   = tid >> 4;
    const int row0 = blockIdx.y * 128;
    const int col0 = blockIdx.x * 128;
    const float* B0 = Bw + (size_t)(col0 >> 6) * cstride;  // cols [col0, col0+64)
    const float* B1 = B0 + cstride;                        // cols [+64, +128)

    float acc[8][8];
    #pragma unroll
    for (int i = 0; i < 8; i++)
        #pragma unroll
        for (int j = 0; j < 8; j++) acc[i][j] = 0.0f;

    for (int k0 = 0; k0 < K; k0 += 16) {
        #pragma unroll
        for (int i = 0; i < 2; i++) {
            int idx = tid + i * 256;                 // 0..511 float4 of A tile
            int m   = idx >> 2;                      // 0..127
            int kk  = (idx & 3) * 4;                 // 0,4,8,12
            float4 a = *(const float4*)(A + (size_t)(row0 + m) * lda + k0 + kk);
            As[kk + 0][m] = a.x; As[kk + 1][m] = a.y;
            As[kk + 2][m] = a.z; As[kk + 3][m] = a.w;
        }
        #pragma unroll
        for (int i = 0; i < 2; i++) {
            int idx = tid + i * 256;                 // 0..511 float4 of B tile
            int kk  = idx >> 5;                      // 0..15
            int n   = (idx & 31) * 4;                // 0..124
            const float* src = (n < 64)
                ? (B0 + (size_t)(k0 + kk) * ldb + n)
                : (B1 + (size_t)(k0 + kk) * ldb + (n - 64));
            *(float4*)&Bs[kk][n] = *(const float4*)src;
        }
        __syncthreads();
        #pragma unroll
        for (int kk = 0; kk < 16; kk++) {
            float4 a0 = *(const float4*)&As[kk][ty * 8];
            float4 a1 = *(const float4*)&As[kk][ty * 8 + 4];
            float4 b0 = *(const float4*)&Bs[kk][tx * 8];
            float4 b1 = *(const float4*)&Bs[kk][tx * 8 + 4];
            float av[8] = {a0.x, a0.y, a0.z, a0.w, a1.x, a1.y, a1.z, a1.w};
            float bv[8] = {b0.x, b0.y, b0.z, b0.w, b1.x, b1.y, b1.z, b1.w};
            #pragma unroll
            for (int i = 0; i < 8; i++)
                #pragma unroll
                for (int j = 0; j < 8; j++)
                    acc[i][j] = fmaf(av[i], bv[j], acc[i][j]);
        }
        __syncthreads();
    }

    #pragma unroll
    for (int i = 0; i < 8; i++) {
        size_t roff = (size_t)(row0 + ty * 8 + i) * ldc;
        #pragma unroll
        for (int jj = 0; jj < 2; jj++) {
            int c = col0 + tx * 8 + jj * 4;
            float4 bb = *(const float4*)(bias + c);
            float4 v;
            v.x = acc[i][jj * 4 + 0] + bb.x;
            v.y = acc[i][jj * 4 + 1] + bb.y;
            v.z = acc[i][jj * 4 + 2] + bb.z;
            v.w = acc[i][jj * 4 + 3] + bb.w;
            if (res) {
                float4 rv = *(const float4*)(res + roff + c);
                v.x += rv.x; v.y += rv.y; v.z += rv.z; v.w += rv.w;
            }
            if (relu) {
                v.x = fmaxf(v.x, 0.f); v.y = fmaxf(v.y, 0.f);
                v.z = fmaxf(v.z, 0.f); v.w = fmaxf(v.w, 0.f);
            }
            *(float4*)(C + roff + c) = v;
        }
    }
}

// ---------------- causal flash attention (fp32) -----------------------------
// grid: (T/128 q-tiles, B*H).  block 256 = 16x16, micro 8 rows x 4 cols.
// Q/K/V layout: [B, T, H*DK] rows, head slice at col h*64.
#define ATTN_SMEM ((64 * 132 + 128 * 68 + 64 * 68) * 4)

__global__ __launch_bounds__(256) void attn_kernel(
    const float* __restrict__ Q, const float* __restrict__ Km,
    const float* __restrict__ V, float* __restrict__ O)
{
    extern __shared__ float sm[];
    float* Qt = sm;                   // [64 d][132]  (Qt[d][r] = Q[r][d])
    float* KP = sm + 64 * 132;        // Kt[64 d][68] then reused as Ps[128 r][68]
    float* Vs = KP + 128 * 68;        // [64 key][68]

    const int tid = threadIdx.x;
    const int tx  = tid & 15;
    const int ty  = tid >> 4;
    const int qt  = blockIdx.x;
    const int bh  = blockIdx.y;
    const int b   = bh >> 3, h = bh & 7;
    const int q0  = qt * 128;
    const size_t base = ((size_t)b * T_) * D_ + h * DK_;
    const float* Qg = Q  + base;
    const float* Kg = Km + base;
    const float* Vg = V  + base;

    // load Q tile transposed into smem
    #pragma unroll
    for (int i = 0; i < 8; i++) {
        int fidx = tid + i * 256;            // 0..2047 float4s
        int r    = fidx >> 4;                // 0..127
        int d    = (fidx & 15) * 4;          // 0..60
        float4 qv = *(const float4*)(Qg + (size_t)(q0 + r) * D_ + d);
        Qt[(d + 0) * 132 + r] = qv.x;
        Qt[(d + 1) * 132 + r] = qv.y;
        Qt[(d + 2) * 132 + r] = qv.z;
        Qt[(d + 3) * 132 + r] = qv.w;
    }

    float m_[8], l_[8], o_[8][4];
    #pragma unroll
    for (int i = 0; i < 8; i++) {
        m_[i] = -1e30f; l_[i] = 0.0f;
        o_[i][0] = o_[i][1] = o_[i][2] = o_[i][3] = 0.0f;
    }

    const int ntile = (q0 >> 6) + 2;          // causal: key tiles 0..(q0+127)/64
    for (int kt = 0; kt < ntile; kt++) {
        const int j0 = kt * 64;
        __syncthreads();                       // protects KP reuse + Qt on iter0
        // load K tile (transposed) and V tile
        #pragma unroll
        for (int i = 0; i < 4; i++) {
            int fidx = tid + i * 256;          // 0..1023 float4s
            int c    = fidx >> 4;              // 0..63 keys
            int d    = (fidx & 15) * 4;
            float4 kv = *(const float4*)(Kg + (size_t)(j0 + c) * D_ + d);
            KP[(d + 0) * 68 + c] = kv.x;
            KP[(d + 1) * 68 + c] = kv.y;
            KP[(d + 2) * 68 + c] = kv.z;
            KP[(d + 3) * 68 + c] = kv.w;
            float4 vv = *(const float4*)(Vg + (size_t)(j0 + c) * D_ + d);
            *(float4*)(Vs + c * 68 + d) = vv;
        }
        __syncthreads();

        // S = Q K^T  (contraction over d = 64)
        float s_[8][4];
        #pragma unroll
        for (int i = 0; i < 8; i++)
            s_[i][0] = s_[i][1] = s_[i][2] = s_[i][3] = 0.0f;
        #pragma unroll 8
        for (int d = 0; d < 64; d++) {
            float4 a0 = *(const float4*)(Qt + d * 132 + ty * 8);
            float4 a1 = *(const float4*)(Qt + d * 132 + ty * 8 + 4);
            float4 bb = *(const float4*)(KP + d * 68 + tx * 4);
            float av[8] = {a0.x, a0.y, a0.z, a0.w, a1.x, a1.y, a1.z, a1.w};
            float bv[4] = {bb.x, bb.y, bb.z, bb.w};
            #pragma unroll
            for (int i = 0; i < 8; i++)
                #pragma unroll
                for (int j = 0; j < 4; j++)
                    s_[i][j] = fmaf(av[i], bv[j], s_[i][j]);
        }

        // causal mask (pre-scale, matches reference) + online softmax update
        #pragma unroll
        for (int i = 0; i < 8; i++) {
            int tg = q0 + ty * 8 + i;
            float rm = -1e30f;
            #pragma unroll
            for (int j = 0; j < 4; j++) {
                int sg = j0 + tx * 4 + j;
                float v = (sg <= tg) ? s_[i][j] * 0.125f : -1e30f;
                s_[i][j] = v;
                rm = fmaxf(rm, v);
            }
            rm = fmaxf(rm, __shfl_xor_sync(0xffffffffu, rm, 1));
            rm = fmaxf(rm, __shfl_xor_sync(0xffffffffu, rm, 2));
            rm = fmaxf(rm, __shfl_xor_sync(0xffffffffu, rm, 4));
            rm = fmaxf(rm, __shfl_xor_sync(0xffffffffu, rm, 8));
            float mn    = fmaxf(m_[i], rm);
            float alpha = __expf(m_[i] - mn);
            m_[i] = mn;
            float ps = 0.0f;
            #pragma unroll
            for (int j = 0; j < 4; j++) {
                float p = __expf(s_[i][j] - mn);
                s_[i][j] = p;
                ps += p;
            }
            ps += __shfl_xor_sync(0xffffffffu, ps, 1);
            ps += __shfl_xor_sync(0xffffffffu, ps, 2);
            ps += __shfl_xor_sync(0xffffffffu, ps, 4);
            ps += __shfl_xor_sync(0xffffffffu, ps, 8);
            l_[i] = l_[i] * alpha + ps;
            #pragma unroll
            for (int j = 0; j < 4; j++) o_[i][j] *= alpha;
        }

        __syncthreads();                       // everyone done reading Kt
        // stage P into smem (overwrites Kt region)
        #pragma unroll
        for (int i = 0; i < 8; i++)
            *(float4*)(KP + (ty * 8 + i) * 68 + tx * 4) =
                make_float4(s_[i][0], s_[i][1], s_[i][2], s_[i][3]);
        __syncthreads();

        // O += P V   (contraction over 64 keys)
        #pragma unroll 4
        for (int j = 0; j < 64; j += 4) {
            float4 vb0 = *(const float4*)(Vs + (j + 0) * 68 + tx * 4);
            float4 vb1 = *(const float4*)(Vs + (j + 1) * 68 + tx * 4);
            float4 vb2 = *(const float4*)(Vs + (j + 2) * 68 + tx * 4);
            float4 vb3 = *(const float4*)(Vs + (j + 3) * 68 + tx * 4);
            #pragma unroll
            for (int i = 0; i < 8; i++) {
                float4 pa = *(const float4*)(KP + (ty * 8 + i) * 68 + j);
                o_[i][0] = fmaf(pa.x, vb0.x, o_[i][0]);
                o_[i][1] = fmaf(pa.x, vb0.y, o_[i][1]);
                o_[i][2] = fmaf(pa.x, vb0.z, o_[i][2]);
                o_[i][3] = fmaf(pa.x, vb0.w, o_[i][3]);
                o_[i][0] = fmaf(pa.y, vb1.x, o_[i][0]);
                o_[i][1] = fmaf(pa.y, vb1.y, o_[i][1]);
                o_[i][2] = fmaf(pa.y, vb1.z, o_[i][2]);
                o_[i][3] = fmaf(pa.y, vb1.w, o_[i][3]);
                o_[i][0] = fmaf(pa.z, vb2.x, o_[i][0]);
                o_[i][1] = fmaf(pa.z, vb2.y, o_[i][1]);
                o_[i][2] = fmaf(pa.z, vb2.z, o_[i][2]);
                o_[i][3] = fmaf(pa.z, vb2.w, o_[i][3]);
                o_[i][0] = fmaf(pa.w, vb3.x, o_[i][0]);
                o_[i][1] = fmaf(pa.w, vb3.y, o_[i][1]);
                o_[i][2] = fmaf(pa.w, vb3.z, o_[i][2]);
                o_[i][3] = fmaf(pa.w, vb3.w, o_[i][3]);
            }
        }
    }

    // normalize and write out (concat-head layout)
    #pragma unroll
    for (int i = 0; i < 8; i++) {
        float inv = 1.0f / l_[i];
        float4 ov = make_float4(o_[i][0] * inv, o_[i][1] * inv,
                                o_[i][2] * inv, o_[i][3] * inv);
        *(float4*)(O + base + (size_t)(q0 + ty * 8 + i) * D_ + tx * 4) = ov;
    }
}

// ---------------- launcher ---------------------------------------------------
extern "C" void kernel_launch(void* const* d_in, const int* in_sizes, int n_in,
                              void* d_out, int out_size)
{
    const float* x   = (const float*)d_in[0];
    const float* Wq  = (const float*)d_in[1];
    const float* bq  = (const float*)d_in[2];
    const float* Wk  = (const float*)d_in[3];
    const float* bk  = (const float*)d_in[4];
    const float* Wv  = (const float*)d_in[5];
    const float* bv  = (const float*)d_in[6];
    const float* Wp  = (const float*)d_in[7];
    const float* bp  = (const float*)d_in[8];
    const float* W1  = (const float*)d_in[9];
    const float* b1  = (const float*)d_in[10];
    const float* W2  = (const float*)d_in[11];
    const float* b2  = (const float*)d_in[12];
    const float* g1  = (const float*)d_in[13];
    const float* be1 = (const float*)d_in[14];
    const float* g2  = (const float*)d_in[15];
    const float* be2 = (const float*)d_in[16];
    float* out = (float*)d_out;

    float *h, *q, *k, *v, *o, *x1, *h2, *ff;
    cudaGetSymbolAddress((void**)&h,  g_h);
    cudaGetSymbolAddress((void**)&q,  g_q);
    cudaGetSymbolAddress((void**)&k,  g_k);
    cudaGetSymbolAddress((void**)&v,  g_v);
    cudaGetSymbolAddress((void**)&o,  g_o);
    cudaGetSymbolAddress((void**)&x1, g_x1);
    cudaGetSymbolAddress((void**)&h2, g_h2);
    cudaGetSymbolAddress((void**)&ff, g_ff);

    cudaFuncSetAttribute(attn_kernel,
                         cudaFuncAttributeMaxDynamicSharedMemorySize, ATTN_SMEM);

    // LN1
    ln_kernel<<<BT_, 128>>>(x, g1, be1, h);

    // QKV projections (head-stacked weights: cstride = D*DK, ldb = DK)
    dim3 g512(D_ / 128, BT_ / 128);
    gemm_kernel<<<g512, 256>>>(h, D_, Wq, D_ * DK_, DK_, bq, nullptr, q, D_, D_, 0);
    gemm_kernel<<<g512, 256>>>(h, D_, Wk, D_ * DK_, DK_, bk, nullptr, k, D_, D_, 0);
    gemm_kernel<<<g512, 256>>>(h, D_, Wv, D_ * DK_, DK_, bv, nullptr, v, D_, D_, 0);

    // causal attention
    attn_kernel<<<dim3(T_ / 128, B_ * H_), 256, ATTN_SMEM>>>(q, k, v, o);

    // output projection + residual (row-major weights: cstride = 64, ldb = N)
    gemm_kernel<<<g512, 256>>>(o, D_, Wp, 64, D_, bp, x, x1, D_, D_, 0);

    // LN2
    ln_kernel<<<BT_, 128>>>(x1, g2, be2, h2);

    // FFN
    gemm_kernel<<<dim3(DFF_ / 128, BT_ / 128), 256>>>(h2, D_, W1, 64, DFF_, b1,
                                                      nullptr, ff, DFF_, D_, 1);
    gemm_kernel<<<g512, 256>>>(ff, DFF_, W2, 64, D_, b2, x1, out, D_, DFF_, 0);
}

// round 4
// speedup vs baseline: 1.0076x; 1.0076x over previous
#include <cuda_runtime.h>
#include <cstdint>

#define B_   4
#define T_   2048
#define D_   512
#define H_   8
#define DK_  64
#define BT_  (B_ * T_)
#define DFF_ 2048

// ---------------- scratch (static device globals; no allocations) ----------
__device__ float g_h [BT_ * D_];
__device__ float g_q [BT_ * D_];   // [B,T,H,DK] flattened = [BT, 512]
__device__ float g_k [BT_ * D_];
__device__ float g_v [BT_ * D_];
__device__ float g_o [BT_ * D_];   // attention output, concat-head layout
__device__ float g_x1[BT_ * D_];
__device__ float g_h2[BT_ * D_];
__device__ float g_ff[BT_ * DFF_];

// ---------------- LayerNorm: one block per row of 512 ----------------------
__global__ __launch_bounds__(128) void ln_kernel(
    const float* __restrict__ x, const float* __restrict__ g,
    const float* __restrict__ b, float* __restrict__ out)
{
    const int row = blockIdx.x;
    const int tid = threadIdx.x;                 // 128 threads * float4 = 512
    float4 v = ((const float4*)(x + (size_t)row * D_))[tid];
    float s  = v.x + v.y + v.z + v.w;
    float ss = v.x * v.x + v.y * v.y + v.z * v.z + v.w * v.w;
    #pragma unroll
    for (int o = 16; o > 0; o >>= 1) {
        s  += __shfl_xor_sync(0xffffffffu, s,  o);
        ss += __shfl_xor_sync(0xffffffffu, ss, o);
    }
    __shared__ float sh_s[4], sh_ss[4];
    if ((tid & 31) == 0) { sh_s[tid >> 5] = s; sh_ss[tid >> 5] = ss; }
    __syncthreads();
    const float tot  = sh_s[0] + sh_s[1] + sh_s[2] + sh_s[3];
    const float tots = sh_ss[0] + sh_ss[1] + sh_ss[2] + sh_ss[3];
    const float mu   = tot  * (1.0f / D_);
    const float var  = tots * (1.0f / D_) - mu * mu;
    const float rstd = rsqrtf(var + 1e-5f);
    float4 gv = ((const float4*)g)[tid];
    float4 bv = ((const float4*)b)[tid];
    float4 r;
    r.x = (v.x - mu) * rstd * gv.x + bv.x;
    r.y = (v.y - mu) * rstd * gv.y + bv.y;
    r.z = (v.z - mu) * rstd * gv.z + bv.z;
    r.w = (v.w - mu) * rstd * gv.w + bv.w;
    ((float4*)(out + (size_t)row * D_))[tid] = r;
}

// ---------------- generic SGEMM 128x128 tile, 8x8 micro-tile ----------------
// C[row, col] = sum_k A[row, k] * B(k, col) (+bias[col]) (+res[row,col]) (relu)
// Weight addressing: addr(k, col) = Bw + (col>>6)*cstride + k*ldb + (col&63)
//   row-major [K,N]      : cstride = 64,     ldb = N
//   head-stacked [H,D,DK]: cstride = D*DK,   ldb = DK
__global__ __launch_bounds__(256) void gemm_kernel(
    const float* __restrict__ A, int lda,
    const float* __restrict__ Bw, int cstride, int ldb,
    const float* __restrict__ bias,
    const float* __restrict__ res,
    float* __restrict__ C, int ldc,
    int K, int relu)
{
    __shared__ __align__(16) float As[16][132];   // transposed: As[k][m]
    __shared__ __align__(16) float Bs[16][132];   // Bs[k][n]

    const int tid  = threadIdx.x;
    const int tx   = tid & 15;
    const int ty   = tid >> 4;
    const int row0 = blockIdx.y * 128;
    const int col0 = blockIdx.x * 128;
    const float* B0 = Bw + (size_t)(col0 >> 6) * cstride;  // cols [col0, col0+64)
    const float* B1 = B0 + cstride;                        // cols [+64, +128)

    float acc[8][8];
    #pragma unroll
    for (int i = 0; i < 8; i++)
        #pragma unroll
        for (int j = 0; j < 8; j++) acc[i][j] = 0.0f;

    for (int k0 = 0; k0 < K; k0 += 16) {
        #pragma unroll
        for (int i = 0; i < 2; i++) {
            int idx = tid + i * 256;                 // 0..511 float4 of A tile
            int m   = idx >> 2;                      // 0..127
            int kk  = (idx & 3) * 4;                 // 0,4,8,12
            float4 a = *(const float4*)(A + (size_t)(row0 + m) * lda + k0 + kk);
            As[kk + 0][m] = a.x; As[kk + 1][m] = a.y;
            As[kk + 2][m] = a.z; As[kk + 3][m] = a.w;
        }
        #pragma unroll
        for (int i = 0; i < 2; i++) {
            int idx = tid + i * 256;                 // 0..511 float4 of B tile
            int kk  = idx >> 5;                      // 0..15
            int n   = (idx & 31) * 4;                // 0..124
            const float* src = (n < 64)
                ? (B0 + (size_t)(k0 + kk) * ldb + n)
                : (B1 + (size_t)(k0 + kk) * ldb + (n - 64));
            *(float4*)&Bs[kk][n] = *(const float4*)src;
        }
        __syncthreads();
        #pragma unroll
        for (int kk = 0; kk < 16; kk++) {
            float4 a0 = *(const float4*)&As[kk][ty * 8];
            float4 a1 = *(const float4*)&As[kk][ty * 8 + 4];
            float4 b0 = *(const float4*)&Bs[kk][tx * 8];
            float4 b1 = *(const float4*)&Bs[kk][tx * 8 + 4];
            float av[8] = {a0.x, a0.y, a0.z, a0.w, a1.x, a1.y, a1.z, a1.w};
            float bv[8] = {b0.x, b0.y, b0.z, b0.w, b1.x, b1.y, b1.z, b1.w};
            #pragma unroll
            for (int i = 0; i < 8; i++)
                #pragma unroll
                for (int j = 0; j < 8; j++)
                    acc[i][j] = fmaf(av[i], bv[j], acc[i][j]);
        }
        __syncthreads();
    }

    #pragma unroll
    for (int i = 0; i < 8; i++) {
        size_t roff = (size_t)(row0 + ty * 8 + i) * ldc;
        #pragma unroll
        for (int jj = 0; jj < 2; jj++) {
            int c = col0 + tx * 8 + jj * 4;
            float4 bb = *(const float4*)(bias + c);
            float4 v;
            v.x = acc[i][jj * 4 + 0] + bb.x;
            v.y = acc[i][jj * 4 + 1] + bb.y;
            v.z = acc[i][jj * 4 + 2] + bb.z;
            v.w = acc[i][jj * 4 + 3] + bb.w;
            if (res) {
                float4 rv = *(const float4*)(res + roff + c);
                v.x += rv.x; v.y += rv.y; v.z += rv.z; v.w += rv.w;
            }
            if (relu) {
                v.x = fmaxf(v.x, 0.f); v.y = fmaxf(v.y, 0.f);
                v.z = fmaxf(v.z, 0.f); v.w = fmaxf(v.w, 0.f);
            }
            *(float4*)(C + roff + c) = v;
        }
    }
}

// ---------------- causal flash attention (fp32) -----------------------------
// grid: (T/128 q-tiles, B*H).  block 256 = 16x16, micro 8 rows x 4 cols.
// Q/K/V layout: [B, T, H*DK] rows, head slice at col h*64.
#define ATTN_SMEM ((64 * 132 + 128 * 68 + 64 * 68) * 4)

__global__ __launch_bounds__(256) void attn_kernel(
    const float* __restrict__ Q, const float* __restrict__ Km,
    const float* __restrict__ V, float* __restrict__ O)
{
    extern __shared__ float sm[];
    float* Qt = sm;                   // [64 d][132]  (Qt[d][r] = Q[r][d])
    float* KP = sm + 64 * 132;        // Kt[64 d][68] then reused as Ps[128 r][68]
    float* Vs = KP + 128 * 68;        // [64 key][68]

    const int tid = threadIdx.x;
    const int tx  = tid & 15;
    const int ty  = tid >> 4;
    const int qt  = blockIdx.x;
    const int bh  = blockIdx.y;
    const int b   = bh >> 3, h = bh & 7;
    const int q0  = qt * 128;
    const size_t base = ((size_t)b * T_) * D_ + h * DK_;
    const float* Qg = Q  + base;
    const float* Kg = Km + base;
    const float* Vg = V  + base;

    // load Q tile transposed into smem
    #pragma unroll
    for (int i = 0; i < 8; i++) {
        int fidx = tid + i * 256;            // 0..2047 float4s
        int r    = fidx >> 4;                // 0..127
        int d    = (fidx & 15) * 4;          // 0..60
        float4 qv = *(const float4*)(Qg + (size_t)(q0 + r) * D_ + d);
        Qt[(d + 0) * 132 + r] = qv.x;
        Qt[(d + 1) * 132 + r] = qv.y;
        Qt[(d + 2) * 132 + r] = qv.z;
        Qt[(d + 3) * 132 + r] = qv.w;
    }

    float m_[8], l_[8], o_[8][4];
    #pragma unroll
    for (int i = 0; i < 8; i++) {
        m_[i] = -1e30f; l_[i] = 0.0f;
        o_[i][0] = o_[i][1] = o_[i][2] = o_[i][3] = 0.0f;
    }

    const int ntile = (q0 >> 6) + 2;          // causal: key tiles 0..(q0+127)/64
    for (int kt = 0; kt < ntile; kt++) {
        const int j0 = kt * 64;
        __syncthreads();                       // protects KP reuse + Qt on iter0
        // load K tile (transposed) and V tile
        #pragma unroll
        for (int i = 0; i < 4; i++) {
            int fidx = tid + i * 256;          // 0..1023 float4s
            int c    = fidx >> 4;              // 0..63 keys
            int d    = (fidx & 15) * 4;
            float4 kv = *(const float4*)(Kg + (size_t)(j0 + c) * D_ + d);
            KP[(d + 0) * 68 + c] = kv.x;
            KP[(d + 1) * 68 + c] = kv.y;
            KP[(d + 2) * 68 + c] = kv.z;
            KP[(d + 3) * 68 + c] = kv.w;
            float4 vv = *(const float4*)(Vg + (size_t)(j0 + c) * D_ + d);
            *(float4*)(Vs + c * 68 + d) = vv;
        }
        __syncthreads();

        // S = Q K^T  (contraction over d = 64)
        float s_[8][4];
        #pragma unroll
        for (int i = 0; i < 8; i++)
            s_[i][0] = s_[i][1] = s_[i][2] = s_[i][3] = 0.0f;
        #pragma unroll 8
        for (int d = 0; d < 64; d++) {
            float4 a0 = *(const float4*)(Qt + d * 132 + ty * 8);
            float4 a1 = *(const float4*)(Qt + d * 132 + ty * 8 + 4);
            float4 bb = *(const float4*)(KP + d * 68 + tx * 4);
            float av[8] = {a0.x, a0.y, a0.z, a0.w, a1.x, a1.y, a1.z, a1.w};
            float bv[4] = {bb.x, bb.y, bb.z, bb.w};
            #pragma unroll
            for (int i = 0; i < 8; i++)
                #pragma unroll
                for (int j = 0; j < 4; j++)
                    s_[i][j] = fmaf(av[i], bv[j], s_[i][j]);
        }

        // causal mask (pre-scale, matches reference) + online softmax update
        #pragma unroll
        for (int i = 0; i < 8; i++) {
            int tg = q0 + ty * 8 + i;
            float rm = -1e30f;
            #pragma unroll
            for (int j = 0; j < 4; j++) {
                int sg = j0 + tx * 4 + j;
                float v = (sg <= tg) ? s_[i][j] * 0.125f : -1e30f;
                s_[i][j] = v;
                rm = fmaxf(rm, v);
            }
            rm = fmaxf(rm, __shfl_xor_sync(0xffffffffu, rm, 1));
            rm = fmaxf(rm, __shfl_xor_sync(0xffffffffu, rm, 2));
            rm = fmaxf(rm, __shfl_xor_sync(0xffffffffu, rm, 4));
            rm = fmaxf(rm, __shfl_xor_sync(0xffffffffu, rm, 8));
            float mn    = fmaxf(m_[i], rm);
            float alpha = __expf(m_[i] - mn);
            m_[i] = mn;
            float ps = 0.0f;
            #pragma unroll
            for (int j = 0; j < 4; j++) {
                float p = __expf(s_[i][j] - mn);
                s_[i][j] = p;
                ps += p;
            }
            ps += __shfl_xor_sync(0xffffffffu, ps, 1);
            ps += __shfl_xor_sync(0xffffffffu, ps, 2);
            ps += __shfl_xor_sync(0xffffffffu, ps, 4);
            ps += __shfl_xor_sync(0xffffffffu, ps, 8);
            l_[i] = l_[i] * alpha + ps;
            #pragma unroll
            for (int j = 0; j < 4; j++) o_[i][j] *= alpha;
        }

        __syncthreads();                       // everyone done reading Kt
        // stage P into smem (overwrites Kt region)
        #pragma unroll
        for (int i = 0; i < 8; i++)
            *(float4*)(KP + (ty * 8 + i) * 68 + tx * 4) =
                make_float4(s_[i][0], s_[i][1], s_[i][2], s_[i][3]);
        __syncthreads();

        // O += P V   (contraction over 64 keys)
        #pragma unroll 4
        for (int j = 0; j < 64; j += 4) {
            float4 vb0 = *(const float4*)(Vs + (j + 0) * 68 + tx * 4);
            float4 vb1 = *(const float4*)(Vs + (j + 1) * 68 + tx * 4);
            float4 vb2 = *(const float4*)(Vs + (j + 2) * 68 + tx * 4);
            float4 vb3 = *(const float4*)(Vs + (j + 3) * 68 + tx * 4);
            #pragma unroll
            for (int i = 0; i < 8; i++) {
                float4 pa = *(const float4*)(KP + (ty * 8 + i) * 68 + j);
                o_[i][0] = fmaf(pa.x, vb0.x, o_[i][0]);
                o_[i][1] = fmaf(pa.x, vb0.y, o_[i][1]);
                o_[i][2] = fmaf(pa.x, vb0.z, o_[i][2]);
                o_[i][3] = fmaf(pa.x, vb0.w, o_[i][3]);
                o_[i][0] = fmaf(pa.y, vb1.x, o_[i][0]);
                o_[i][1] = fmaf(pa.y, vb1.y, o_[i][1]);
                o_[i][2] = fmaf(pa.y, vb1.z, o_[i][2]);
                o_[i][3] = fmaf(pa.y, vb1.w, o_[i][3]);
                o_[i][0] = fmaf(pa.z, vb2.x, o_[i][0]);
                o_[i][1] = fmaf(pa.z, vb2.y, o_[i][1]);
                o_[i][2] = fmaf(pa.z, vb2.z, o_[i][2]);
                o_[i][3] = fmaf(pa.z, vb2.w, o_[i][3]);
                o_[i][0] = fmaf(pa.w, vb3.x, o_[i][0]);
                o_[i][1] = fmaf(pa.w, vb3.y, o_[i][1]);
                o_[i][2] = fmaf(pa.w, vb3.z, o_[i][2]);
                o_[i][3] = fmaf(pa.w, vb3.w, o_[i][3]);
            }
        }
    }

    // normalize and write out (concat-head layout)
    #pragma unroll
    for (int i = 0; i < 8; i++) {
        float inv = 1.0f / l_[i];
        float4 ov = make_float4(o_[i][0] * inv, o_[i][1] * inv,
                                o_[i][2] * inv, o_[i][3] * inv);
        *(float4*)(O + base + (size_t)(q0 + ty * 8 + i) * D_ + tx * 4) = ov;
    }
}

// ---------------- launcher ---------------------------------------------------
extern "C" void kernel_launch(void* const* d_in, const int* in_sizes, int n_in,
                              void* d_out, int out_size)
{
    const float* x   = (const float*)d_in[0];
    const float* Wq  = (const float*)d_in[1];
    const float* bq  = (const float*)d_in[2];
    const float* Wk  = (const float*)d_in[3];
    const float* bk  = (const float*)d_in[4];
    const float* Wv  = (const float*)d_in[5];
    const float* bv  = (const float*)d_in[6];
    const float* Wp  = (const float*)d_in[7];
    const float* bp  = (const float*)d_in[8];
    const float* W1  = (const float*)d_in[9];
    const float* b1  = (const float*)d_in[10];
    const float* W2  = (const float*)d_in[11];
    const float* b2  = (const float*)d_in[12];
    const float* g1  = (const float*)d_in[13];
    const float* be1 = (const float*)d_in[14];
    const float* g2  = (const float*)d_in[15];
    const float* be2 = (const float*)d_in[16];
    float* out = (float*)d_out;

    float *h, *q, *k, *v, *o, *x1, *h2, *ff;
    cudaGetSymbolAddress((void**)&h,  g_h);
    cudaGetSymbolAddress((void**)&q,  g_q);
    cudaGetSymbolAddress((void**)&k,  g_k);
    cudaGetSymbolAddress((void**)&v,  g_v);
    cudaGetSymbolAddress((void**)&o,  g_o);
    cudaGetSymbolAddress((void**)&x1, g_x1);
    cudaGetSymbolAddress((void**)&h2, g_h2);
    cudaGetSymbolAddress((void**)&ff, g_ff);

    cudaFuncSetAttribute(attn_kernel,
                         cudaFuncAttributeMaxDynamicSharedMemorySize, ATTN_SMEM);

    // LN1
    ln_kernel<<<BT_, 128>>>(x, g1, be1, h);

    // QKV projections (head-stacked weights: cstride = D*DK, ldb = DK)
    dim3 g512(D_ / 128, BT_ / 128);
    gemm_kernel<<<g512, 256>>>(h, D_, Wq, D_ * DK_, DK_, bq, nullptr, q, D_, D_, 0);
    gemm_kernel<<<g512, 256>>>(h, D_, Wk, D_ * DK_, DK_, bk, nullptr, k, D_, D_, 0);
    gemm_kernel<<<g512, 256>>>(h, D_, Wv, D_ * DK_, DK_, bv, nullptr, v, D_, D_, 0);

    // causal attention
    attn_kernel<<<dim3(T_ / 128, B_ * H_), 256, ATTN_SMEM>>>(q, k, v, o);

    // output projection + residual (row-major weights: cstride = 64, ldb = N)
    gemm_kernel<<<g512, 256>>>(o, D_, Wp, 64, D_, bp, x, x1, D_, D_, 0);

    // LN2
    ln_kernel<<<BT_, 128>>>(x1, g2, be2, h2);

    // FFN
    gemm_kernel<<<dim3(DFF_ / 128, BT_ / 128), 256>>>(h2, D_, W1, 64, DFF_, b1,
                                                      nullptr, ff, DFF_, D_, 1);
    gemm_kernel<<<g512, 256>>>(ff, DFF_, W2, 64, D_, b2, x1, out, D_, DFF_, 0);
}

// round 5
// speedup vs baseline: 2.1517x; 2.1355x over previous
#include <cuda_runtime.h>
#include <cstdint>

#define B_   4
#define T_   2048
#define D_   512
#define H_   8
#define DK_  64
#define BT_  (B_ * T_)
#define DFF_ 2048

// ---------------- scratch (static device globals; no allocations) ----------
__device__ float g_h [BT_ * D_];
__device__ float g_q [BT_ * D_];   // [B,T,H,DK] flattened = [BT, 512]
__device__ float g_k [BT_ * D_];
__device__ float g_v [BT_ * D_];
__device__ float g_o [BT_ * D_];   // attention output, concat-head layout
__device__ float g_x1[BT_ * D_];
__device__ float g_h2[BT_ * D_];
__device__ float g_ff[BT_ * DFF_];

// ---------------- LayerNorm: one block per row of 512 ----------------------
__global__ __launch_bounds__(128) void ln_kernel(
    const float* __restrict__ x, const float* __restrict__ g,
    const float* __restrict__ b, float* __restrict__ out)
{
    const int row = blockIdx.x;
    const int tid = threadIdx.x;                 // 128 threads * float4 = 512
    float4 v = ((const float4*)(x + (size_t)row * D_))[tid];
    float s  = v.x + v.y + v.z + v.w;
    float ss = v.x * v.x + v.y * v.y + v.z * v.z + v.w * v.w;
    #pragma unroll
    for (int o = 16; o > 0; o >>= 1) {
        s  += __shfl_xor_sync(0xffffffffu, s,  o);
        ss += __shfl_xor_sync(0xffffffffu, ss, o);
    }
    __shared__ float sh_s[4], sh_ss[4];
    if ((tid & 31) == 0) { sh_s[tid >> 5] = s; sh_ss[tid >> 5] = ss; }
    __syncthreads();
    const float tot  = sh_s[0] + sh_s[1] + sh_s[2] + sh_s[3];
    const float tots = sh_ss[0] + sh_ss[1] + sh_ss[2] + sh_ss[3];
    const float mu   = tot  * (1.0f / D_);
    const float var  = tots * (1.0f / D_) - mu * mu;
    const float rstd = rsqrtf(var + 1e-5f);
    float4 gv = ((const float4*)g)[tid];
    float4 bv = ((const float4*)b)[tid];
    float4 r;
    r.x = (v.x - mu) * rstd * gv.x + bv.x;
    r.y = (v.y - mu) * rstd * gv.y + bv.y;
    r.z = (v.z - mu) * rstd * gv.z + bv.z;
    r.w = (v.w - mu) * rstd * gv.w + bv.w;
    ((float4*)(out + (size_t)row * D_))[tid] = r;
}

// ---------------- tf32 helpers ----------------------------------------------
__device__ __forceinline__ uint32_t f2tf32(float x) {
    uint32_t u;
    asm("cvt.rna.tf32.f32 %0, %1;" : "=r"(u) : "f"(x));
    return u;
}

__device__ __forceinline__ void mma_tf32(float* d, const uint32_t* a,
                                         const uint32_t* b) {
    asm volatile(
        "mma.sync.aligned.m16n8k8.row.col.f32.tf32.tf32.f32 "
        "{%0,%1,%2,%3}, {%4,%5,%6,%7}, {%8,%9}, {%0,%1,%2,%3};"
        : "+f"(d[0]), "+f"(d[1]), "+f"(d[2]), "+f"(d[3])
        : "r"(a[0]), "r"(a[1]), "r"(a[2]), "r"(a[3]),
          "r"(b[0]), "r"(b[1]));
}

// ---------------- tf32 tensor-core GEMM, 128x128 tile -----------------------
// C[row, col] = sum_k A[row, k] * B(k, col) (+bias[col]) (+res[row,col]) (relu)
// Weight addressing: addr(k, col) = Bw + (col>>6)*cstride + k*ldb + (col&63)
//   row-major [K,N]      : cstride = 64,     ldb = N
//   head-stacked [H,D,DK]: cstride = D*DK,   ldb = DK
// 8 warps: warp tile 64x32 (wm in {0,1}, wn in {0..3}); mma m16n8k8, BK=32.
#define PAD_A 36
#define PAD_B 136
__global__ __launch_bounds__(256) void gemm_kernel(
    const float* __restrict__ A, int lda,
    const float* __restrict__ Bw, int cstride, int ldb,
    const float* __restrict__ bias,
    const float* __restrict__ res,
    float* __restrict__ C, int ldc,
    int K, int relu)
{
    __shared__ __align__(16) float As[128][PAD_A];  // m-major (tf32 bits)
    __shared__ __align__(16) float Bs[32][PAD_B];   // k-major (tf32 bits)

    const int tid  = threadIdx.x;
    const int lane = tid & 31;
    const int wid  = tid >> 5;
    const int wm   = wid & 1;        // row block of 64
    const int wn   = wid >> 1;       // col block of 32
    const int row0 = blockIdx.y * 128;
    const int col0 = blockIdx.x * 128;
    const float* B0 = Bw + (size_t)(col0 >> 6) * cstride;  // cols [col0, +64)
    const float* B1 = B0 + cstride;                        // cols [+64, +128)

    const int r = lane >> 2;         // 0..7
    const int c = lane & 3;          // 0..3

    float acc[4][4][4];
    #pragma unroll
    for (int mi = 0; mi < 4; mi++)
        #pragma unroll
        for (int ni = 0; ni < 4; ni++)
            acc[mi][ni][0] = acc[mi][ni][1] = acc[mi][ni][2] = acc[mi][ni][3] = 0.f;

    for (int k0 = 0; k0 < K; k0 += 32) {
        // --- load A tile 128 rows x 32 k (coalesced: 8 threads per row) ---
        #pragma unroll
        for (int i = 0; i < 4; i++) {
            int idx = tid + i * 256;            // 0..1023 float4s
            int m   = idx >> 3;                 // 0..127
            int kk  = (idx & 7) * 4;            // 0,4,...,28
            float4 a = *(const float4*)(A + (size_t)(row0 + m) * lda + k0 + kk);
            uint4 u;
            u.x = f2tf32(a.x); u.y = f2tf32(a.y);
            u.z = f2tf32(a.z); u.w = f2tf32(a.w);
            *(uint4*)&As[m][kk] = u;
        }
        // --- load B tile 32 k x 128 n ---
        #pragma unroll
        for (int i = 0; i < 4; i++) {
            int idx = tid + i * 256;            // 0..1023 float4s
            int kk  = idx >> 5;                 // 0..31
            int n4  = (idx & 31) * 4;           // 0..124
            const float* src = (n4 < 64)
                ? (B0 + (size_t)(k0 + kk) * ldb + n4)
                : (B1 + (size_t)(k0 + kk) * ldb + (n4 - 64));
            float4 b = *(const float4*)src;
            uint4 u;
            u.x = f2tf32(b.x); u.y = f2tf32(b.y);
            u.z = f2tf32(b.z); u.w = f2tf32(b.w);
            *(uint4*)&Bs[kk][n4] = u;
        }
        __syncthreads();

        #pragma unroll
        for (int ks = 0; ks < 32; ks += 8) {
            uint32_t af[4][4], bf[4][2];
            #pragma unroll
            for (int mi = 0; mi < 4; mi++) {
                int m = wm * 64 + mi * 16 + r;
                af[mi][0] = __float_as_uint(As[m    ][ks + c]);
                af[mi][1] = __float_as_uint(As[m + 8][ks + c]);
                af[mi][2] = __float_as_uint(As[m    ][ks + c + 4]);
                af[mi][3] = __float_as_uint(As[m + 8][ks + c + 4]);
            }
            #pragma unroll
            for (int ni = 0; ni < 4; ni++) {
                int n = wn * 32 + ni * 8 + r;
                bf[ni][0] = __float_as_uint(Bs[ks + c    ][n]);
                bf[ni][1] = __float_as_uint(Bs[ks + c + 4][n]);
            }
            #pragma unroll
            for (int mi = 0; mi < 4; mi++)
                #pragma unroll
                for (int ni = 0; ni < 4; ni++)
                    mma_tf32(acc[mi][ni], af[mi], bf[ni]);
        }
        __syncthreads();
    }

    // --- epilogue: bias (+res) (relu), fragment layout c0/c1 adjacent cols ---
    #pragma unroll
    for (int mi = 0; mi < 4; mi++) {
        const int row_a = row0 + wm * 64 + mi * 16 + r;
        const size_t ro0 = (size_t)row_a * ldc;
        const size_t ro1 = (size_t)(row_a + 8) * ldc;
        #pragma unroll
        for (int ni = 0; ni < 4; ni++) {
            const int col_a = col0 + wn * 32 + ni * 8 + 2 * c;
            float2 bb = *(const float2*)(bias + col_a);
            float v0 = acc[mi][ni][0] + bb.x;
            float v1 = acc[mi][ni][1] + bb.y;
            float v2 = acc[mi][ni][2] + bb.x;
            float v3 = acc[mi][ni][3] + bb.y;
            if (res) {
                float2 r0v = *(const float2*)(res + ro0 + col_a);
                float2 r1v = *(const float2*)(res + ro1 + col_a);
                v0 += r0v.x; v1 += r0v.y; v2 += r1v.x; v3 += r1v.y;
            }
            if (relu) {
                v0 = fmaxf(v0, 0.f); v1 = fmaxf(v1, 0.f);
                v2 = fmaxf(v2, 0.f); v3 = fmaxf(v3, 0.f);
            }
            *(float2*)(C + ro0 + col_a) = make_float2(v0, v1);
            *(float2*)(C + ro1 + col_a) = make_float2(v2, v3);
        }
    }
}

// ---------------- causal flash attention (fp32) -----------------------------
// grid: (T/128 q-tiles, B*H).  block 256 = 16x16, micro 8 rows x 4 cols.
// Q/K/V layout: [B, T, H*DK] rows, head slice at col h*64.
#define ATTN_SMEM ((64 * 132 + 128 * 68 + 64 * 68) * 4)

__global__ __launch_bounds__(256) void attn_kernel(
    const float* __restrict__ Q, const float* __restrict__ Km,
    const float* __restrict__ V, float* __restrict__ O)
{
    extern __shared__ float sm[];
    float* Qt = sm;                   // [64 d][132]  (Qt[d][r] = Q[r][d])
    float* KP = sm + 64 * 132;        // Kt[64 d][68] then reused as Ps[128 r][68]
    float* Vs = KP + 128 * 68;        // [64 key][68]

    const int tid = threadIdx.x;
    const int tx  = tid & 15;
    const int ty  = tid >> 4;
    const int qt  = blockIdx.x;
    const int bh  = blockIdx.y;
    const int b   = bh >> 3, h = bh & 7;
    const int q0  = qt * 128;
    const size_t base = ((size_t)b * T_) * D_ + h * DK_;
    const float* Qg = Q  + base;
    const float* Kg = Km + base;
    const float* Vg = V  + base;

    // load Q tile transposed into smem
    #pragma unroll
    for (int i = 0; i < 8; i++) {
        int fidx = tid + i * 256;            // 0..2047 float4s
        int r    = fidx >> 4;                // 0..127
        int d    = (fidx & 15) * 4;          // 0..60
        float4 qv = *(const float4*)(Qg + (size_t)(q0 + r) * D_ + d);
        Qt[(d + 0) * 132 + r] = qv.x;
        Qt[(d + 1) * 132 + r] = qv.y;
        Qt[(d + 2) * 132 + r] = qv.z;
        Qt[(d + 3) * 132 + r] = qv.w;
    }

    float m_[8], l_[8], o_[8][4];
    #pragma unroll
    for (int i = 0; i < 8; i++) {
        m_[i] = -1e30f; l_[i] = 0.0f;
        o_[i][0] = o_[i][1] = o_[i][2] = o_[i][3] = 0.0f;
    }

    const int ntile = (q0 >> 6) + 2;          // causal: key tiles 0..(q0+127)/64
    for (int kt = 0; kt < ntile; kt++) {
        const int j0 = kt * 64;
        __syncthreads();                       // protects KP reuse + Qt on iter0
        // load K tile (transposed) and V tile
        #pragma unroll
        for (int i = 0; i < 4; i++) {
            int fidx = tid + i * 256;          // 0..1023 float4s
            int c    = fidx >> 4;              // 0..63 keys
            int d    = (fidx & 15) * 4;
            float4 kv = *(const float4*)(Kg + (size_t)(j0 + c) * D_ + d);
            KP[(d + 0) * 68 + c] = kv.x;
            KP[(d + 1) * 68 + c] = kv.y;
            KP[(d + 2) * 68 + c] = kv.z;
            KP[(d + 3) * 68 + c] = kv.w;
            float4 vv = *(const float4*)(Vg + (size_t)(j0 + c) * D_ + d);
            *(float4*)(Vs + c * 68 + d) = vv;
        }
        __syncthreads();

        // S = Q K^T  (contraction over d = 64)
        float s_[8][4];
        #pragma unroll
        for (int i = 0; i < 8; i++)
            s_[i][0] = s_[i][1] = s_[i][2] = s_[i][3] = 0.0f;
        #pragma unroll 8
        for (int d = 0; d < 64; d++) {
            float4 a0 = *(const float4*)(Qt + d * 132 + ty * 8);
            float4 a1 = *(const float4*)(Qt + d * 132 + ty * 8 + 4);
            float4 bb = *(const float4*)(KP + d * 68 + tx * 4);
            float av[8] = {a0.x, a0.y, a0.z, a0.w, a1.x, a1.y, a1.z, a1.w};
            float bv[4] = {bb.x, bb.y, bb.z, bb.w};
            #pragma unroll
            for (int i = 0; i < 8; i++)
                #pragma unroll
                for (int j = 0; j < 4; j++)
                    s_[i][j] = fmaf(av[i], bv[j], s_[i][j]);
        }

        // causal mask (pre-scale, matches reference) + online softmax update
        #pragma unroll
        for (int i = 0; i < 8; i++) {
            int tg = q0 + ty * 8 + i;
            float rm = -1e30f;
            #pragma unroll
            for (int j = 0; j < 4; j++) {
                int sg = j0 + tx * 4 + j;
                float v = (sg <= tg) ? s_[i][j] * 0.125f : -1e30f;
                s_[i][j] = v;
                rm = fmaxf(rm, v);
            }
            rm = fmaxf(rm, __shfl_xor_sync(0xffffffffu, rm, 1));
            rm = fmaxf(rm, __shfl_xor_sync(0xffffffffu, rm, 2));
            rm = fmaxf(rm, __shfl_xor_sync(0xffffffffu, rm, 4));
            rm = fmaxf(rm, __shfl_xor_sync(0xffffffffu, rm, 8));
            float mn    = fmaxf(m_[i], rm);
            float alpha = __expf(m_[i] - mn);
            m_[i] = mn;
            float ps = 0.0f;
            #pragma unroll
            for (int j = 0; j < 4; j++) {
                float p = __expf(s_[i][j] - mn);
                s_[i][j] = p;
                ps += p;
            }
            ps += __shfl_xor_sync(0xffffffffu, ps, 1);
            ps += __shfl_xor_sync(0xffffffffu, ps, 2);
            ps += __shfl_xor_sync(0xffffffffu, ps, 4);
            ps += __shfl_xor_sync(0xffffffffu, ps, 8);
            l_[i] = l_[i] * alpha + ps;
            #pragma unroll
            for (int j = 0; j < 4; j++) o_[i][j] *= alpha;
        }

        __syncthreads();                       // everyone done reading Kt
        // stage P into smem (overwrites Kt region)
        #pragma unroll
        for (int i = 0; i < 8; i++)
            *(float4*)(KP + (ty * 8 + i) * 68 + tx * 4) =
                make_float4(s_[i][0], s_[i][1], s_[i][2], s_[i][3]);
        __syncthreads();

        // O += P V   (contraction over 64 keys)
        #pragma unroll 4
        for (int j = 0; j < 64; j += 4) {
            float4 vb0 = *(const float4*)(Vs + (j + 0) * 68 + tx * 4);
            float4 vb1 = *(const float4*)(Vs + (j + 1) * 68 + tx * 4);
            float4 vb2 = *(const float4*)(Vs + (j + 2) * 68 + tx * 4);
            float4 vb3 = *(const float4*)(Vs + (j + 3) * 68 + tx * 4);
            #pragma unroll
            for (int i = 0; i < 8; i++) {
                float4 pa = *(const float4*)(KP + (ty * 8 + i) * 68 + j);
                o_[i][0] = fmaf(pa.x, vb0.x, o_[i][0]);
                o_[i][1] = fmaf(pa.x, vb0.y, o_[i][1]);
                o_[i][2] = fmaf(pa.x, vb0.z, o_[i][2]);
                o_[i][3] = fmaf(pa.x, vb0.w, o_[i][3]);
                o_[i][0] = fmaf(pa.y, vb1.x, o_[i][0]);
                o_[i][1] = fmaf(pa.y, vb1.y, o_[i][1]);
                o_[i][2] = fmaf(pa.y, vb1.z, o_[i][2]);
                o_[i][3] = fmaf(pa.y, vb1.w, o_[i][3]);
                o_[i][0] = fmaf(pa.z, vb2.x, o_[i][0]);
                o_[i][1] = fmaf(pa.z, vb2.y, o_[i][1]);
                o_[i][2] = fmaf(pa.z, vb2.z, o_[i][2]);
                o_[i][3] = fmaf(pa.z, vb2.w, o_[i][3]);
                o_[i][0] = fmaf(pa.w, vb3.x, o_[i][0]);
                o_[i][1] = fmaf(pa.w, vb3.y, o_[i][1]);
                o_[i][2] = fmaf(pa.w, vb3.z, o_[i][2]);
                o_[i][3] = fmaf(pa.w, vb3.w, o_[i][3]);
            }
        }
    }

    // normalize and write out (concat-head layout)
    #pragma unroll
    for (int i = 0; i < 8; i++) {
        float inv = 1.0f / l_[i];
        float4 ov = make_float4(o_[i][0] * inv, o_[i][1] * inv,
                                o_[i][2] * inv, o_[i][3] * inv);
        *(float4*)(O + base + (size_t)(q0 + ty * 8 + i) * D_ + tx * 4) = ov;
    }
}

// ---------------- launcher ---------------------------------------------------
extern "C" void kernel_launch(void* const* d_in, const int* in_sizes, int n_in,
                              void* d_out, int out_size)
{
    const float* x   = (const float*)d_in[0];
    const float* Wq  = (const float*)d_in[1];
    const float* bq  = (const float*)d_in[2];
    const float* Wk  = (const float*)d_in[3];
    const float* bk  = (const float*)d_in[4];
    const float* Wv  = (const float*)d_in[5];
    const float* bv  = (const float*)d_in[6];
    const float* Wp  = (const float*)d_in[7];
    const float* bp  = (const float*)d_in[8];
    const float* W1  = (const float*)d_in[9];
    const float* b1  = (const float*)d_in[10];
    const float* W2  = (const float*)d_in[11];
    const float* b2  = (const float*)d_in[12];
    const float* g1  = (const float*)d_in[13];
    const float* be1 = (const float*)d_in[14];
    const float* g2  = (const float*)d_in[15];
    const float* be2 = (const float*)d_in[16];
    float* out = (float*)d_out;

    float *h, *q, *k, *v, *o, *x1, *h2, *ff;
    cudaGetSymbolAddress((void**)&h,  g_h);
    cudaGetSymbolAddress((void**)&q,  g_q);
    cudaGetSymbolAddress((void**)&k,  g_k);
    cudaGetSymbolAddress((void**)&v,  g_v);
    cudaGetSymbolAddress((void**)&o,  g_o);
    cudaGetSymbolAddress((void**)&x1, g_x1);
    cudaGetSymbolAddress((void**)&h2, g_h2);
    cudaGetSymbolAddress((void**)&ff, g_ff);

    cudaFuncSetAttribute(attn_kernel,
                         cudaFuncAttributeMaxDynamicSharedMemorySize, ATTN_SMEM);

    // LN1
    ln_kernel<<<BT_, 128>>>(x, g1, be1, h);

    // QKV projections (head-stacked weights: cstride = D*DK, ldb = DK)
    dim3 g512(D_ / 128, BT_ / 128);
    gemm_kernel<<<g512, 256>>>(h, D_, Wq, D_ * DK_, DK_, bq, nullptr, q, D_, D_, 0);
    gemm_kernel<<<g512, 256>>>(h, D_, Wk, D_ * DK_, DK_, bk, nullptr, k, D_, D_, 0);
    gemm_kernel<<<g512, 256>>>(h, D_, Wv, D_ * DK_, DK_, bv, nullptr, v, D_, D_, 0);

    // causal attention
    attn_kernel<<<dim3(T_ / 128, B_ * H_), 256, ATTN_SMEM>>>(q, k, v, o);

    // output projection + residual (row-major weights: cstride = 64, ldb = N)
    gemm_kernel<<<g512, 256>>>(o, D_, Wp, 64, D_, bp, x, x1, D_, D_, 0);

    // LN2
    ln_kernel<<<BT_, 128>>>(x1, g2, be2, h2);

    // FFN
    gemm_kernel<<<dim3(DFF_ / 128, BT_ / 128), 256>>>(h2, D_, W1, 64, DFF_, b1,
                                                      nullptr, ff, DFF_, D_, 1);
    gemm_kernel<<<g512, 256>>>(ff, DFF_, W2, 64, D_, b2, x1, out, D_, DFF_, 0);
}

// round 6
// speedup vs baseline: 3.4102x; 1.5849x over previous
#include <cuda_runtime.h>
#include <cstdint>

#define B_   4
#define T_   2048
#define D_   512
#define H_   8
#define DK_  64
#define BT_  (B_ * T_)
#define DFF_ 2048

// ---------------- scratch (static device globals; no allocations) ----------
__device__ float g_h [BT_ * D_];
__device__ float g_q [BT_ * D_];   // [B,T,H,DK] flattened = [BT, 512]
__device__ float g_k [BT_ * D_];
__device__ float g_v [BT_ * D_];
__device__ float g_o [BT_ * D_];   // attention output, concat-head layout
__device__ float g_x1[BT_ * D_];
__device__ float g_h2[BT_ * D_];
__device__ float g_ff[BT_ * DFF_];

// ---------------- LayerNorm: one block per row of 512 ----------------------
__global__ __launch_bounds__(128) void ln_kernel(
    const float* __restrict__ x, const float* __restrict__ g,
    const float* __restrict__ b, float* __restrict__ out)
{
    const int row = blockIdx.x;
    const int tid = threadIdx.x;                 // 128 threads * float4 = 512
    float4 v = ((const float4*)(x + (size_t)row * D_))[tid];
    float s  = v.x + v.y + v.z + v.w;
    float ss = v.x * v.x + v.y * v.y + v.z * v.z + v.w * v.w;
    #pragma unroll
    for (int o = 16; o > 0; o >>= 1) {
        s  += __shfl_xor_sync(0xffffffffu, s,  o);
        ss += __shfl_xor_sync(0xffffffffu, ss, o);
    }
    __shared__ float sh_s[4], sh_ss[4];
    if ((tid & 31) == 0) { sh_s[tid >> 5] = s; sh_ss[tid >> 5] = ss; }
    __syncthreads();
    const float tot  = sh_s[0] + sh_s[1] + sh_s[2] + sh_s[3];
    const float tots = sh_ss[0] + sh_ss[1] + sh_ss[2] + sh_ss[3];
    const float mu   = tot  * (1.0f / D_);
    const float var  = tots * (1.0f / D_) - mu * mu;
    const float rstd = rsqrtf(var + 1e-5f);
    float4 gv = ((const float4*)g)[tid];
    float4 bv = ((const float4*)b)[tid];
    float4 r;
    r.x = (v.x - mu) * rstd * gv.x + bv.x;
    r.y = (v.y - mu) * rstd * gv.y + bv.y;
    r.z = (v.z - mu) * rstd * gv.z + bv.z;
    r.w = (v.w - mu) * rstd * gv.w + bv.w;
    ((float4*)(out + (size_t)row * D_))[tid] = r;
}

// ---------------- tf32 helpers ----------------------------------------------
__device__ __forceinline__ uint32_t f2tf32(float x) {
    uint32_t u;
    asm("cvt.rna.tf32.f32 %0, %1;" : "=r"(u) : "f"(x));
    return u;
}

__device__ __forceinline__ void mma_tf32(float* d, const uint32_t* a,
                                         const uint32_t* b) {
    asm volatile(
        "mma.sync.aligned.m16n8k8.row.col.f32.tf32.tf32.f32 "
        "{%0,%1,%2,%3}, {%4,%5,%6,%7}, {%8,%9}, {%0,%1,%2,%3};"
        : "+f"(d[0]), "+f"(d[1]), "+f"(d[2]), "+f"(d[3])
        : "r"(a[0]), "r"(a[1]), "r"(a[2]), "r"(a[3]),
          "r"(b[0]), "r"(b[1]));
}

// ---------------- tf32 tensor-core GEMM, 128x128 tile -----------------------
// C[row, col] = sum_k A[row, k] * B(k, col) (+bias[col]) (+res[row,col]) (relu)
// Weight addressing: addr(k, col) = Bw + (col>>6)*cstride + k*ldb + (col&63)
//   row-major [K,N]      : cstride = 64,     ldb = N
//   head-stacked [H,D,DK]: cstride = D*DK,   ldb = DK
// 8 warps: warp tile 64x32 (wm in {0,1}, wn in {0..3}); mma m16n8k8, BK=32.
#define PAD_A 36
#define PAD_B 136
__global__ __launch_bounds__(256) void gemm_kernel(
    const float* __restrict__ A, int lda,
    const float* __restrict__ Bw, int cstride, int ldb,
    const float* __restrict__ bias,
    const float* __restrict__ res,
    float* __restrict__ C, int ldc,
    int K, int relu)
{
    __shared__ __align__(16) float As[128][PAD_A];  // m-major (tf32 bits)
    __shared__ __align__(16) float Bs[32][PAD_B];   // k-major (tf32 bits)

    const int tid  = threadIdx.x;
    const int lane = tid & 31;
    const int wid  = tid >> 5;
    const int wm   = wid & 1;        // row block of 64
    const int wn   = wid >> 1;       // col block of 32
    const int row0 = blockIdx.y * 128;
    const int col0 = blockIdx.x * 128;
    const float* B0 = Bw + (size_t)(col0 >> 6) * cstride;  // cols [col0, +64)
    const float* B1 = B0 + cstride;                        // cols [+64, +128)

    const int r = lane >> 2;         // 0..7
    const int c = lane & 3;          // 0..3

    float acc[4][4][4];
    #pragma unroll
    for (int mi = 0; mi < 4; mi++)
        #pragma unroll
        for (int ni = 0; ni < 4; ni++)
            acc[mi][ni][0] = acc[mi][ni][1] = acc[mi][ni][2] = acc[mi][ni][3] = 0.f;

    for (int k0 = 0; k0 < K; k0 += 32) {
        // --- load A tile 128 rows x 32 k (coalesced: 8 threads per row) ---
        #pragma unroll
        for (int i = 0; i < 4; i++) {
            int idx = tid + i * 256;            // 0..1023 float4s
            int m   = idx >> 3;                 // 0..127
            int kk  = (idx & 7) * 4;            // 0,4,...,28
            float4 a = *(const float4*)(A + (size_t)(row0 + m) * lda + k0 + kk);
            uint4 u;
            u.x = f2tf32(a.x); u.y = f2tf32(a.y);
            u.z = f2tf32(a.z); u.w = f2tf32(a.w);
            *(uint4*)&As[m][kk] = u;
        }
        // --- load B tile 32 k x 128 n ---
        #pragma unroll
        for (int i = 0; i < 4; i++) {
            int idx = tid + i * 256;            // 0..1023 float4s
            int kk  = idx >> 5;                 // 0..31
            int n4  = (idx & 31) * 4;           // 0..124
            const float* src = (n4 < 64)
                ? (B0 + (size_t)(k0 + kk) * ldb + n4)
                : (B1 + (size_t)(k0 + kk) * ldb + (n4 - 64));
            float4 b = *(const float4*)src;
            uint4 u;
            u.x = f2tf32(b.x); u.y = f2tf32(b.y);
            u.z = f2tf32(b.z); u.w = f2tf32(b.w);
            *(uint4*)&Bs[kk][n4] = u;
        }
        __syncthreads();

        #pragma unroll
        for (int ks = 0; ks < 32; ks += 8) {
            uint32_t af[4][4], bf[4][2];
            #pragma unroll
            for (int mi = 0; mi < 4; mi++) {
                int m = wm * 64 + mi * 16 + r;
                af[mi][0] = __float_as_uint(As[m    ][ks + c]);
                af[mi][1] = __float_as_uint(As[m + 8][ks + c]);
                af[mi][2] = __float_as_uint(As[m    ][ks + c + 4]);
                af[mi][3] = __float_as_uint(As[m + 8][ks + c + 4]);
            }
            #pragma unroll
            for (int ni = 0; ni < 4; ni++) {
                int n = wn * 32 + ni * 8 + r;
                bf[ni][0] = __float_as_uint(Bs[ks + c    ][n]);
                bf[ni][1] = __float_as_uint(Bs[ks + c + 4][n]);
            }
            #pragma unroll
            for (int mi = 0; mi < 4; mi++)
                #pragma unroll
                for (int ni = 0; ni < 4; ni++)
                    mma_tf32(acc[mi][ni], af[mi], bf[ni]);
        }
        __syncthreads();
    }

    // --- epilogue: bias (+res) (relu), fragment layout c0/c1 adjacent cols ---
    #pragma unroll
    for (int mi = 0; mi < 4; mi++) {
        const int row_a = row0 + wm * 64 + mi * 16 + r;
        const size_t ro0 = (size_t)row_a * ldc;
        const size_t ro1 = (size_t)(row_a + 8) * ldc;
        #pragma unroll
        for (int ni = 0; ni < 4; ni++) {
            const int col_a = col0 + wn * 32 + ni * 8 + 2 * c;
            float2 bb = *(const float2*)(bias + col_a);
            float v0 = acc[mi][ni][0] + bb.x;
            float v1 = acc[mi][ni][1] + bb.y;
            float v2 = acc[mi][ni][2] + bb.x;
            float v3 = acc[mi][ni][3] + bb.y;
            if (res) {
                float2 r0v = *(const float2*)(res + ro0 + col_a);
                float2 r1v = *(const float2*)(res + ro1 + col_a);
                v0 += r0v.x; v1 += r0v.y; v2 += r1v.x; v3 += r1v.y;
            }
            if (relu) {
                v0 = fmaxf(v0, 0.f); v1 = fmaxf(v1, 0.f);
                v2 = fmaxf(v2, 0.f); v3 = fmaxf(v3, 0.f);
            }
            *(float2*)(C + ro0 + col_a) = make_float2(v0, v1);
            *(float2*)(C + ro1 + col_a) = make_float2(v2, v3);
        }
    }
}

// ---------------- tf32 tensor-core causal flash attention -------------------
// grid: (T/128 q-tiles, B*H). block 256 = 8 warps; warp w owns query rows
// [w*16, w*16+16). k-tile = 64 keys. mma m16n8k8 tf32.
// Smem: Qs[128][68] (tf32 bits), KP[128][68] (K tile, later overlaid by P),
//       Vs[64][72]. All fragment LDS patterns bank-conflict-free.
#define QP 68
#define VP 72
#define ATTN_SMEM ((128 * QP + 128 * QP + 64 * VP) * 4)

__global__ __launch_bounds__(256) void attn_kernel(
    const float* __restrict__ Q, const float* __restrict__ Km,
    const float* __restrict__ V, float* __restrict__ O)
{
    extern __shared__ float sm[];
    float* Qs = sm;                  // [128][68]  Q, tf32 bits
    float* KP = sm + 128 * QP;       // [128][68]  K rows 0..63; P rows 0..127
    float* Vs = KP + 128 * QP;       // [64][72]   V, tf32 bits

    const int tid  = threadIdx.x;
    const int lane = tid & 31;
    const int w    = tid >> 5;       // warp id: query rows w*16..w*16+15
    const int r    = lane >> 2;      // 0..7
    const int c    = lane & 3;       // 0..3
    const int qt   = blockIdx.x;
    const int bh   = blockIdx.y;
    const int b    = bh >> 3, h = bh & 7;
    const int q0   = qt * 128;
    const size_t base = ((size_t)b * T_) * D_ + h * DK_;
    const float* Qg = Q  + base;
    const float* Kg = Km + base;
    const float* Vg = V  + base;

    // ---- load Q tile (convert to tf32) ----
    #pragma unroll
    for (int i = 0; i < 8; i++) {
        int fidx = tid + i * 256;            // 0..2047 float4s
        int row  = fidx >> 4;                // 0..127
        int d4   = (fidx & 15) * 4;          // 0..60
        float4 qv = *(const float4*)(Qg + (size_t)(q0 + row) * D_ + d4);
        uint4 u;
        u.x = f2tf32(qv.x); u.y = f2tf32(qv.y);
        u.z = f2tf32(qv.z); u.w = f2tf32(qv.w);
        *(uint4*)&Qs[row * QP + d4] = u;
    }

    // online-softmax state: thread owns rows (w*16+r) and (w*16+r+8)
    float m_[2] = {-1e30f, -1e30f};
    float l_[2] = {0.0f, 0.0f};
    float oacc[8][4];
    #pragma unroll
    for (int ni = 0; ni < 8; ni++)
        oacc[ni][0] = oacc[ni][1] = oacc[ni][2] = oacc[ni][3] = 0.0f;

    const int ntile = (q0 >> 6) + 2;          // causal: key tiles 0..(q0+127)/64
    for (int kt = 0; kt < ntile; kt++) {
        const int j0 = kt * 64;
        __syncthreads();                       // prev-iter Vs/KP reads done
        // ---- load K and V tiles (convert to tf32) ----
        #pragma unroll
        for (int i = 0; i < 4; i++) {
            int fidx = tid + i * 256;          // 0..1023 float4s
            int s    = fidx >> 4;              // 0..63
            int d4   = (fidx & 15) * 4;
            float4 kv = *(const float4*)(Kg + (size_t)(j0 + s) * D_ + d4);
            uint4 uk;
            uk.x = f2tf32(kv.x); uk.y = f2tf32(kv.y);
            uk.z = f2tf32(kv.z); uk.w = f2tf32(kv.w);
            *(uint4*)&KP[s * QP + d4] = uk;
            float4 vv = *(const float4*)(Vg + (size_t)(j0 + s) * D_ + d4);
            uint4 uv;
            uv.x = f2tf32(vv.x); uv.y = f2tf32(vv.y);
            uv.z = f2tf32(vv.z); uv.w = f2tf32(vv.w);
            *(uint4*)&Vs[s * VP + d4] = uv;
        }
        __syncthreads();

        // ---- S = Q K^T : [16 q] x [64 s], contraction over d=64 ----
        float sacc[8][4];
        #pragma unroll
        for (int ni = 0; ni < 8; ni++)
            sacc[ni][0] = sacc[ni][1] = sacc[ni][2] = sacc[ni][3] = 0.0f;
        #pragma unroll
        for (int ks = 0; ks < 64; ks += 8) {
            uint32_t af[4];
            const int qa = (w * 16 + r) * QP + ks + c;
            af[0] = __float_as_uint(Qs[qa]);
            af[1] = __float_as_uint(Qs[qa + 8 * QP]);
            af[2] = __float_as_uint(Qs[qa + 4]);
            af[3] = __float_as_uint(Qs[qa + 8 * QP + 4]);
            #pragma unroll
            for (int ni = 0; ni < 8; ni++) {
                uint32_t bf[2];
                const int kb = (ni * 8 + r) * QP + ks + c;
                bf[0] = __float_as_uint(KP[kb]);
                bf[1] = __float_as_uint(KP[kb + 4]);
                mma_tf32(sacc[ni], af, bf);
            }
        }

        // ---- causal mask (pre-scale, matches ref) + online softmax ----
        #pragma unroll
        for (int ri = 0; ri < 2; ri++) {
            const int tg = q0 + w * 16 + r + ri * 8;
            float rm = -1e30f;
            #pragma unroll
            for (int ni = 0; ni < 8; ni++) {
                #pragma unroll
                for (int jj = 0; jj < 2; jj++) {
                    int sg = j0 + ni * 8 + 2 * c + jj;
                    float v = (sg <= tg) ? sacc[ni][ri * 2 + jj] * 0.125f
                                         : -1e30f;
                    sacc[ni][ri * 2 + jj] = v;
                    rm = fmaxf(rm, v);
                }
            }
            rm = fmaxf(rm, __shfl_xor_sync(0xffffffffu, rm, 1));
            rm = fmaxf(rm, __shfl_xor_sync(0xffffffffu, rm, 2));
            const float mn    = fmaxf(m_[ri], rm);
            const float alpha = __expf(m_[ri] - mn);
            m_[ri] = mn;
            float ps = 0.0f;
            #pragma unroll
            for (int ni = 0; ni < 8; ni++) {
                #pragma unroll
                for (int jj = 0; jj < 2; jj++) {
                    float p = __expf(sacc[ni][ri * 2 + jj] - mn);
                    sacc[ni][ri * 2 + jj] = p;
                    ps += p;
                }
            }
            ps += __shfl_xor_sync(0xffffffffu, ps, 1);
            ps += __shfl_xor_sync(0xffffffffu, ps, 2);
            l_[ri] = l_[ri] * alpha + ps;
            #pragma unroll
            for (int ni = 0; ni < 8; ni++) {
                oacc[ni][ri * 2 + 0] *= alpha;
                oacc[ni][ri * 2 + 1] *= alpha;
            }
        }

        __syncthreads();   // all warps done reading K from KP
        // ---- stage P (tf32) into KP, warp-private rows ----
        #pragma unroll
        for (int ni = 0; ni < 8; ni++) {
            float2 p0, p1;
            p0.x = __uint_as_float(f2tf32(sacc[ni][0]));
            p0.y = __uint_as_float(f2tf32(sacc[ni][1]));
            p1.x = __uint_as_float(f2tf32(sacc[ni][2]));
            p1.y = __uint_as_float(f2tf32(sacc[ni][3]));
            *(float2*)&KP[(w * 16 + r)     * QP + ni * 8 + 2 * c] = p0;
            *(float2*)&KP[(w * 16 + r + 8) * QP + ni * 8 + 2 * c] = p1;
        }
        __syncwarp();

        // ---- O += P V : contraction over s=64, output cols d=64 ----
        #pragma unroll
        for (int ks = 0; ks < 64; ks += 8) {
            uint32_t af[4];
            const int pa = (w * 16 + r) * QP + ks + c;
            af[0] = __float_as_uint(KP[pa]);
            af[1] = __float_as_uint(KP[pa + 8 * QP]);
            af[2] = __float_as_uint(KP[pa + 4]);
            af[3] = __float_as_uint(KP[pa + 8 * QP + 4]);
            #pragma unroll
            for (int ni = 0; ni < 8; ni++) {
                uint32_t bf[2];
                bf[0] = __float_as_uint(Vs[(ks + c)     * VP + ni * 8 + r]);
                bf[1] = __float_as_uint(Vs[(ks + c + 4) * VP + ni * 8 + r]);
                mma_tf32(oacc[ni], af, bf);
            }
        }
    }

    // ---- normalize and write out (concat-head layout) ----
    const float inv0 = 1.0f / l_[0];
    const float inv1 = 1.0f / l_[1];
    const int row0g = q0 + w * 16 + r;
    #pragma unroll
    for (int ni = 0; ni < 8; ni++) {
        const int col = ni * 8 + 2 * c;
        *(float2*)(O + base + (size_t)row0g * D_ + col) =
            make_float2(oacc[ni][0] * inv0, oacc[ni][1] * inv0);
        *(float2*)(O + base + (size_t)(row0g + 8) * D_ + col) =
            make_float2(oacc[ni][2] * inv1, oacc[ni][3] * inv1);
    }
}

// ---------------- launcher ---------------------------------------------------
extern "C" void kernel_launch(void* const* d_in, const int* in_sizes, int n_in,
                              void* d_out, int out_size)
{
    const float* x   = (const float*)d_in[0];
    const float* Wq  = (const float*)d_in[1];
    const float* bq  = (const float*)d_in[2];
    const float* Wk  = (const float*)d_in[3];
    const float* bk  = (const float*)d_in[4];
    const float* Wv  = (const float*)d_in[5];
    const float* bv  = (const float*)d_in[6];
    const float* Wp  = (const float*)d_in[7];
    const float* bp  = (const float*)d_in[8];
    const float* W1  = (const float*)d_in[9];
    const float* b1  = (const float*)d_in[10];
    const float* W2  = (const float*)d_in[11];
    const float* b2  = (const float*)d_in[12];
    const float* g1  = (const float*)d_in[13];
    const float* be1 = (const float*)d_in[14];
    const float* g2  = (const float*)d_in[15];
    const float* be2 = (const float*)d_in[16];
    float* out = (float*)d_out;

    float *h, *q, *k, *v, *o, *x1, *h2, *ff;
    cudaGetSymbolAddress((void**)&h,  g_h);
    cudaGetSymbolAddress((void**)&q,  g_q);
    cudaGetSymbolAddress((void**)&k,  g_k);
    cudaGetSymbolAddress((void**)&v,  g_v);
    cudaGetSymbolAddress((void**)&o,  g_o);
    cudaGetSymbolAddress((void**)&x1, g_x1);
    cudaGetSymbolAddress((void**)&h2, g_h2);
    cudaGetSymbolAddress((void**)&ff, g_ff);

    cudaFuncSetAttribute(attn_kernel,
                         cudaFuncAttributeMaxDynamicSharedMemorySize, ATTN_SMEM);

    // LN1
    ln_kernel<<<BT_, 128>>>(x, g1, be1, h);

    // QKV projections (head-stacked weights: cstride = D*DK, ldb = DK)
    dim3 g512(D_ / 128, BT_ / 128);
    gemm_kernel<<<g512, 256>>>(h, D_, Wq, D_ * DK_, DK_, bq, nullptr, q, D_, D_, 0);
    gemm_kernel<<<g512, 256>>>(h, D_, Wk, D_ * DK_, DK_, bk, nullptr, k, D_, D_, 0);
    gemm_kernel<<<g512, 256>>>(h, D_, Wv, D_ * DK_, DK_, bv, nullptr, v, D_, D_, 0);

    // causal attention (tensor-core)
    attn_kernel<<<dim3(T_ / 128, B_ * H_), 256, ATTN_SMEM>>>(q, k, v, o);

    // output projection + residual (row-major weights: cstride = 64, ldb = N)
    gemm_kernel<<<g512, 256>>>(o, D_, Wp, 64, D_, bp, x, x1, D_, D_, 0);

    // LN2
    ln_kernel<<<BT_, 128>>>(x1, g2, be2, h2);

    // FFN
    gemm_kernel<<<dim3(DFF_ / 128, BT_ / 128), 256>>>(h2, D_, W1, 64, DFF_, b1,
                                                      nullptr, ff, DFF_, D_, 1);
    gemm_kernel<<<g512, 256>>>(ff, DFF_, W2, 64, D_, b2, x1, out, D_, DFF_, 0);
}